// round 2
// baseline (speedup 1.0000x reference)
#include <cuda_runtime.h>

// FourierAttention1d — linear attention, reassociated + output-projection folded.
//
//   KV[b,h,d,e] = sum_n LN(v Wk^T + kb)[n,h,d] * (v Wv^T + vb)[n,h,e]
//   G[b,h,d,c]  = sum_e KV[b,h,d,e] * o_w[c, h*64+e]
//   out[b,n,c]  = ( sum_{h,d} LN(v Wq^T + qb)[n,h,d] * G[b,h,d,c] + o_b[c] ) / N
//
// Kernel 1: K/V projection + LN(K) + KV outer-product accumulation (atomicAdd partials)
// Kernel 2: fold KV with o_w into G  (tiny)
// Kernel 3: Q projection + LN + Q@G + bias + 1/N

#define B_   4
#define N_   8192
#define CIN_ 64
#define D_   64
#define H_   8
#define HD_  512

// scratch (allocation-free rule: __device__ globals)
__device__ float g_KV[B_ * H_ * D_ * D_];   // [b][h][d][e]
__device__ float g_G [B_ * H_ * D_ * D_];   // [b][h][d][c]

__global__ void zero_kv_kernel() {
    int i = blockIdx.x * blockDim.x + threadIdx.x;
    if (i < B_ * H_ * D_ * D_) g_KV[i] = 0.0f;
}

// ---------------------------------------------------------------------------
// Kernel 1: grid (CH=16 chunks, H, B), 256 threads.
// Each block: one (b,h), 512 tokens, tiles of 16 tokens.
// ---------------------------------------------------------------------------
__global__ __launch_bounds__(256) void kv_kernel(
    const float* __restrict__ v,
    const float* __restrict__ Wk, const float* __restrict__ kb,
    const float* __restrict__ Wv, const float* __restrict__ vb,
    const float* __restrict__ lnw, const float* __restrict__ lnb)
{
    const int chunk = blockIdx.x;
    const int h     = blockIdx.y;
    const int b     = blockIdx.z;
    const int tid   = threadIdx.x;

    __shared__ __align__(16) float sWk[64][64];   // [c][d] (transposed)
    __shared__ __align__(16) float sWv[64][64];   // [c][d]
    __shared__ float sKb[64], sVb[64], sLw[64], sLb[64];
    __shared__ __align__(16) float sV[16][68];
    __shared__ __align__(16) float sK[16][68];
    __shared__ __align__(16) float sU[16][68];

    // stage per-head weights (transposed for per-d float4 reads)
    for (int i = tid; i < 64 * 64; i += 256) {
        int d = i >> 6, c = i & 63;
        sWk[c][d] = Wk[(h * 64 + d) * 64 + c];
        sWv[c][d] = Wv[(h * 64 + d) * 64 + c];
    }
    if (tid < 64) {
        sKb[tid] = kb[h * 64 + tid];
        sVb[tid] = vb[h * 64 + tid];
        sLw[tid] = lnw[h * 64 + tid];
        sLb[tid] = lnb[h * 64 + tid];
    }

    const int r  = tid >> 4;          // token row within tile (0..15)  [Phase B]
    const int d0 = (tid & 15) * 4;    // 4-wide column group (0..60)    [Phase B]
    const int dr = (tid >> 4) * 4;    // KV row group this thread owns  [Phase D]
    const int ec = (tid & 15) * 4;    // KV col group this thread owns  [Phase D]
    float acc[4][4] = {};

    const int n_base = b * N_ + chunk * 512;

    for (int t0 = 0; t0 < 512; t0 += 16) {
        // ---- Phase A: load v tile [16][64]
        __syncthreads();   // protect sV/sK/sU from previous iteration readers
        for (int i = tid; i < 16 * 64; i += 256) {
            int rr = i >> 6, c = i & 63;
            sV[rr][c] = v[(n_base + t0 + rr) * 64 + c];
        }
        __syncthreads();

        // ---- Phase B: project k,vv — thread computes (r, d0..d0+3) for both
        float ka0 = 0.f, ka1 = 0.f, ka2 = 0.f, ka3 = 0.f;
        float ua0 = 0.f, ua1 = 0.f, ua2 = 0.f, ua3 = 0.f;
        #pragma unroll 16
        for (int c = 0; c < 64; c++) {
            float vv = sV[r][c];
            float4 wk = *(const float4*)&sWk[c][d0];
            float4 wv = *(const float4*)&sWv[c][d0];
            ka0 = fmaf(vv, wk.x, ka0); ka1 = fmaf(vv, wk.y, ka1);
            ka2 = fmaf(vv, wk.z, ka2); ka3 = fmaf(vv, wk.w, ka3);
            ua0 = fmaf(vv, wv.x, ua0); ua1 = fmaf(vv, wv.y, ua1);
            ua2 = fmaf(vv, wv.z, ua2); ua3 = fmaf(vv, wv.w, ua3);
        }
        ka0 += sKb[d0 + 0]; ka1 += sKb[d0 + 1]; ka2 += sKb[d0 + 2]; ka3 += sKb[d0 + 3];
        ua0 += sVb[d0 + 0]; ua1 += sVb[d0 + 1]; ua2 += sVb[d0 + 2]; ua3 += sVb[d0 + 3];
        *(float4*)&sK[r][d0] = make_float4(ka0, ka1, ka2, ka3);
        *(float4*)&sU[r][d0] = make_float4(ua0, ua1, ua2, ua3);
        __syncthreads();

        // ---- Phase C: LayerNorm rows of sK (warp w handles rows 2w, 2w+1)
        {
            int w = tid >> 5, lane = tid & 31;
            #pragma unroll
            for (int rr2 = 0; rr2 < 2; rr2++) {
                int rr = w * 2 + rr2;
                float x0 = sK[rr][lane], x1 = sK[rr][lane + 32];
                float s  = x0 + x1;
                float s2 = x0 * x0 + x1 * x1;
                #pragma unroll
                for (int o = 16; o > 0; o >>= 1) {
                    s  += __shfl_xor_sync(0xffffffffu, s,  o);
                    s2 += __shfl_xor_sync(0xffffffffu, s2, o);
                }
                float mu  = s * (1.0f / 64.0f);
                float var = fmaxf(s2 * (1.0f / 64.0f) - mu * mu, 0.0f);
                float inv = rsqrtf(var + 1e-5f);
                sK[rr][lane]      = (x0 - mu) * inv * sLw[lane]      + sLb[lane];
                sK[rr][lane + 32] = (x1 - mu) * inv * sLw[lane + 32] + sLb[lane + 32];
            }
        }
        __syncthreads();

        // ---- Phase D: outer-product accumulate (thread owns KV[dr..dr+3][ec..ec+3])
        #pragma unroll
        for (int t = 0; t < 16; t++) {
            float4 kk = *(const float4*)&sK[t][dr];   // k rows this thread owns
            float4 uu = *(const float4*)&sU[t][ec];   // v cols this thread owns
            acc[0][0] = fmaf(kk.x, uu.x, acc[0][0]); acc[0][1] = fmaf(kk.x, uu.y, acc[0][1]);
            acc[0][2] = fmaf(kk.x, uu.z, acc[0][2]); acc[0][3] = fmaf(kk.x, uu.w, acc[0][3]);
            acc[1][0] = fmaf(kk.y, uu.x, acc[1][0]); acc[1][1] = fmaf(kk.y, uu.y, acc[1][1]);
            acc[1][2] = fmaf(kk.y, uu.z, acc[1][2]); acc[1][3] = fmaf(kk.y, uu.w, acc[1][3]);
            acc[2][0] = fmaf(kk.z, uu.x, acc[2][0]); acc[2][1] = fmaf(kk.z, uu.y, acc[2][1]);
            acc[2][2] = fmaf(kk.z, uu.z, acc[2][2]); acc[2][3] = fmaf(kk.z, uu.w, acc[2][3]);
            acc[3][0] = fmaf(kk.w, uu.x, acc[3][0]); acc[3][1] = fmaf(kk.w, uu.y, acc[3][1]);
            acc[3][2] = fmaf(kk.w, uu.z, acc[3][2]); acc[3][3] = fmaf(kk.w, uu.w, acc[3][3]);
        }
    }

    {
        float* kvp = &g_KV[(b * H_ + h) * 64 * 64];
        #pragma unroll
        for (int i = 0; i < 4; i++)
            #pragma unroll
            for (int j = 0; j < 4; j++)
                atomicAdd(&kvp[(dr + i) * 64 + ec + j], acc[i][j]);
    }
}

// ---------------------------------------------------------------------------
// Kernel 2: fold G[b,h,d,c] = sum_e KV[b,h,d,e] * o_w[c, h*64+e]
// grid (H, B), 256 threads. Tiny kernel.
// ---------------------------------------------------------------------------
__global__ __launch_bounds__(256) void fold_kernel(const float* __restrict__ ow)
{
    const int h = blockIdx.x, b = blockIdx.y, tid = threadIdx.x;
    __shared__ __align__(16) float sKVt[64][64];  // [e][d]
    __shared__ __align__(16) float sOw[64][64];   // [e][c]

    const float* kvp = &g_KV[(b * H_ + h) * 64 * 64];
    for (int i = tid; i < 64 * 64; i += 256) {
        int d = i >> 6, e = i & 63;
        sKVt[e][d] = kvp[d * 64 + e];
    }
    for (int i = tid; i < 64 * 64; i += 256) {
        int c = i >> 6, e = i & 63;
        sOw[e][c] = ow[c * HD_ + h * 64 + e];
    }
    __syncthreads();

    const int d0 = (tid >> 4) * 4, c0 = (tid & 15) * 4;
    float acc[4][4] = {};
    #pragma unroll 16
    for (int e = 0; e < 64; e++) {
        float4 kk = *(const float4*)&sKVt[e][d0];
        float4 cc = *(const float4*)&sOw[e][c0];
        acc[0][0] = fmaf(kk.x, cc.x, acc[0][0]); acc[0][1] = fmaf(kk.x, cc.y, acc[0][1]);
        acc[0][2] = fmaf(kk.x, cc.z, acc[0][2]); acc[0][3] = fmaf(kk.x, cc.w, acc[0][3]);
        acc[1][0] = fmaf(kk.y, cc.x, acc[1][0]); acc[1][1] = fmaf(kk.y, cc.y, acc[1][1]);
        acc[1][2] = fmaf(kk.y, cc.z, acc[1][2]); acc[1][3] = fmaf(kk.y, cc.w, acc[1][3]);
        acc[2][0] = fmaf(kk.z, cc.x, acc[2][0]); acc[2][1] = fmaf(kk.z, cc.y, acc[2][1]);
        acc[2][2] = fmaf(kk.z, cc.z, acc[2][2]); acc[2][3] = fmaf(kk.z, cc.w, acc[2][3]);
        acc[3][0] = fmaf(kk.w, cc.x, acc[3][0]); acc[3][1] = fmaf(kk.w, cc.y, acc[3][1]);
        acc[3][2] = fmaf(kk.w, cc.z, acc[3][2]); acc[3][3] = fmaf(kk.w, cc.w, acc[3][3]);
    }

    float* gp = &g_G[(b * H_ + h) * 64 * 64];
    #pragma unroll
    for (int i = 0; i < 4; i++)
        #pragma unroll
        for (int j = 0; j < 4; j++)
            gp[(d0 + i) * 64 + c0 + j] = acc[i][j];
}

// ---------------------------------------------------------------------------
// Kernel 3: Q proj + LN + Q@G + bias, /N.  grid (CH=64 chunks, B), 256 threads.
// Each block: 128 tokens (8 tiles of 16), loops over heads accumulating out.
// ---------------------------------------------------------------------------
__global__ __launch_bounds__(256) void qout_kernel(
    const float* __restrict__ v,
    const float* __restrict__ Wq, const float* __restrict__ qb,
    const float* __restrict__ lnw, const float* __restrict__ lnb,
    const float* __restrict__ ob,
    float* __restrict__ out)
{
    const int chunk = blockIdx.x, b = blockIdx.y, tid = threadIdx.x;

    __shared__ __align__(16) float sW[64][64];    // [c][d]
    __shared__ __align__(16) float sG[64][64];    // [d][c]
    __shared__ __align__(16) float sV[16][68];
    __shared__ __align__(16) float sQ[16][68];
    __shared__ float sQb[64], sLw[64], sLb[64], sOb[64];

    if (tid < 64) sOb[tid] = ob[tid];

    const int r  = tid >> 4;          // token row (0..15)
    const int c4 = (tid & 15) * 4;    // column group

    const int n_base = b * N_ + chunk * 128;

    for (int t0 = 0; t0 < 128; t0 += 16) {
        __syncthreads();
        for (int i = tid; i < 16 * 64; i += 256) {
            int rr = i >> 6, c = i & 63;
            sV[rr][c] = v[(n_base + t0 + rr) * 64 + c];
        }

        float oa0 = 0.f, oa1 = 0.f, oa2 = 0.f, oa3 = 0.f;

        for (int h = 0; h < H_; h++) {
            __syncthreads();   // protect sW/sG/sQ from previous h readers (and sV writers above)
            for (int i = tid; i < 64 * 64; i += 256) {
                int d = i >> 6, c = i & 63;
                sW[c][d] = Wq[(h * 64 + d) * 64 + c];
                sG[d][c] = g_G[(b * H_ + h) * 64 * 64 + i];
            }
            if (tid < 64) {
                sQb[tid] = qb[h * 64 + tid];
                sLw[tid] = lnw[h * 64 + tid];
                sLb[tid] = lnb[h * 64 + tid];
            }
            __syncthreads();

            // project q: thread (r, c4..c4+3)
            float q0 = 0.f, q1 = 0.f, q2 = 0.f, q3 = 0.f;
            #pragma unroll 16
            for (int c = 0; c < 64; c++) {
                float vv = sV[r][c];
                float4 w = *(const float4*)&sW[c][c4];
                q0 = fmaf(vv, w.x, q0); q1 = fmaf(vv, w.y, q1);
                q2 = fmaf(vv, w.z, q2); q3 = fmaf(vv, w.w, q3);
            }
            q0 += sQb[c4 + 0]; q1 += sQb[c4 + 1]; q2 += sQb[c4 + 2]; q3 += sQb[c4 + 3];
            *(float4*)&sQ[r][c4] = make_float4(q0, q1, q2, q3);
            __syncthreads();

            // LN rows of sQ
            {
                int w = tid >> 5, lane = tid & 31;
                #pragma unroll
                for (int rr2 = 0; rr2 < 2; rr2++) {
                    int rr = w * 2 + rr2;
                    float x0 = sQ[rr][lane], x1 = sQ[rr][lane + 32];
                    float s  = x0 + x1;
                    float s2 = x0 * x0 + x1 * x1;
                    #pragma unroll
                    for (int o = 16; o > 0; o >>= 1) {
                        s  += __shfl_xor_sync(0xffffffffu, s,  o);
                        s2 += __shfl_xor_sync(0xffffffffu, s2, o);
                    }
                    float mu  = s * (1.0f / 64.0f);
                    float var = fmaxf(s2 * (1.0f / 64.0f) - mu * mu, 0.0f);
                    float inv = rsqrtf(var + 1e-5f);
                    sQ[rr][lane]      = (x0 - mu) * inv * sLw[lane]      + sLb[lane];
                    sQ[rr][lane + 32] = (x1 - mu) * inv * sLw[lane + 32] + sLb[lane + 32];
                }
            }
            __syncthreads();

            // accumulate out[r][c4..] += q[r][:] @ G[:, c4..]
            #pragma unroll 16
            for (int d = 0; d < 64; d++) {
                float qq = sQ[r][d];
                float4 g = *(const float4*)&sG[d][c4];
                oa0 = fmaf(qq, g.x, oa0); oa1 = fmaf(qq, g.y, oa1);
                oa2 = fmaf(qq, g.z, oa2); oa3 = fmaf(qq, g.w, oa3);
            }
        }
        __syncthreads();

        const float inv_n = 1.0f / (float)N_;
        float4 o;
        o.x = (oa0 + sOb[c4 + 0]) * inv_n;
        o.y = (oa1 + sOb[c4 + 1]) * inv_n;
        o.z = (oa2 + sOb[c4 + 2]) * inv_n;
        o.w = (oa3 + sOb[c4 + 3]) * inv_n;
        *(float4*)&out[(n_base + t0 + r) * 64 + c4] = o;
    }
}

// ---------------------------------------------------------------------------
extern "C" void kernel_launch(void* const* d_in, const int* in_sizes, int n_in,
                              void* d_out, int out_size)
{
    const float* v     = (const float*)d_in[0];
    const float* Wq_w  = (const float*)d_in[1];
    const float* Wq_b  = (const float*)d_in[2];
    const float* Wk_w  = (const float*)d_in[3];
    const float* Wk_b  = (const float*)d_in[4];
    const float* Wv_w  = (const float*)d_in[5];
    const float* Wv_b  = (const float*)d_in[6];
    const float* lnq_w = (const float*)d_in[7];
    const float* lnq_b = (const float*)d_in[8];
    const float* lnk_w = (const float*)d_in[9];
    const float* lnk_b = (const float*)d_in[10];
    const float* o_w   = (const float*)d_in[11];
    const float* o_b   = (const float*)d_in[12];
    float* out = (float*)d_out;

    zero_kv_kernel<<<512, 256>>>();
    kv_kernel<<<dim3(16, H_, B_), 256>>>(v, Wk_w, Wk_b, Wv_w, Wv_b, lnk_w, lnk_b);
    fold_kernel<<<dim3(H_, B_), 256>>>(o_w);
    qout_kernel<<<dim3(64, B_), 256>>>(v, Wq_w, Wq_b, lnq_w, lnq_b, o_b, out);
}

// round 3
// speedup vs baseline: 2.6202x; 2.6202x over previous
#include <cuda_runtime.h>

// FourierAttention1d — linear attention, reassociated + output-projection folded.
//
//   KV[b,h,d,e] = sum_n LN(v Wk^T + kb)[n,h,d] * (v Wv^T + vb)[n,h,e]
//   G[b,h,d,c]  = sum_e KV[b,h,d,e] * o_w[c, h*64+e]
//   out[b,n,c]  = ( sum_{h,d} LN(v Wq^T + qb)[n,h,d] * G[b,h,d,c] + o_b[c] ) / N
//
// R3: 4x4 register tiling, 64-token tiles, weights amortized per block,
//     dynamic smem (>48KB static limit).

#define B_   4
#define N_   8192
#define H_   8
#define HD_  512

__device__ float g_KV[B_ * H_ * 64 * 64];   // [b][h][d][e]
__device__ float g_G [B_ * H_ * 64 * 64];   // [b][h][d][c]

__global__ void zero_kv_kernel() {
    int i = blockIdx.x * blockDim.x + threadIdx.x;
    if (i < B_ * H_ * 64 * 64) g_KV[i] = 0.0f;
}

// a[4] (x) b[4] -> acc[16], fully unrolled constant indices (stays in regs)
__device__ __forceinline__ void op4x4(float4 a, float4 b, float* acc) {
    acc[ 0] = fmaf(a.x, b.x, acc[ 0]); acc[ 1] = fmaf(a.x, b.y, acc[ 1]);
    acc[ 2] = fmaf(a.x, b.z, acc[ 2]); acc[ 3] = fmaf(a.x, b.w, acc[ 3]);
    acc[ 4] = fmaf(a.y, b.x, acc[ 4]); acc[ 5] = fmaf(a.y, b.y, acc[ 5]);
    acc[ 6] = fmaf(a.y, b.z, acc[ 6]); acc[ 7] = fmaf(a.y, b.w, acc[ 7]);
    acc[ 8] = fmaf(a.z, b.x, acc[ 8]); acc[ 9] = fmaf(a.z, b.y, acc[ 9]);
    acc[10] = fmaf(a.z, b.z, acc[10]); acc[11] = fmaf(a.z, b.w, acc[11]);
    acc[12] = fmaf(a.w, b.x, acc[12]); acc[13] = fmaf(a.w, b.y, acc[13]);
    acc[14] = fmaf(a.w, b.z, acc[14]); acc[15] = fmaf(a.w, b.w, acc[15]);
}

// ---------------------------------------------------------------------------
// Kernel 1: grid (8 chunks, H, B), 256 threads. Block owns (b,h) x 1024 tokens.
// Dynamic smem layout (floats):
//   sWk[64*64] @0, sWv[64*64] @4096, sVt[64*68] @8192 ([cin][token]),
//   sK[64*68] @12544 ([token][d]), sU[64*68] @16896,
//   sKb @21248, sVb @21312, sLw @21376, sLb @21440  (total 21504 f = 86016 B)
// ---------------------------------------------------------------------------
#define KV_SMEM_BYTES (21504 * 4)

__global__ __launch_bounds__(256) void kv_kernel(
    const float* __restrict__ v,
    const float* __restrict__ Wk, const float* __restrict__ kb,
    const float* __restrict__ Wv, const float* __restrict__ vb,
    const float* __restrict__ lnw, const float* __restrict__ lnb)
{
    extern __shared__ float sm[];
    float* sWk = sm;
    float* sWv = sm + 4096;
    float* sVt = sm + 8192;
    float* sK  = sm + 12544;
    float* sU  = sm + 16896;
    float* sKb = sm + 21248;
    float* sVb = sm + 21312;
    float* sLw = sm + 21376;
    float* sLb = sm + 21440;

    const int chunk = blockIdx.x, h = blockIdx.y, b = blockIdx.z;
    const int tid = threadIdx.x;
    const int ty = tid >> 4, tx = tid & 15;
    const int t4 = ty * 4;     // token group (proj) / KV row group (outer)
    const int d4 = tx * 4;     // dim group (proj)   / KV col group (outer)

    // stage weights transposed: sWk[c*64+d] = Wk[(h*64+d)*64+c]
    for (int i = tid; i < 4096; i += 256) {
        int d = i >> 6, c = i & 63;
        sWk[c * 64 + d] = Wk[(h * 64 + d) * 64 + c];
        sWv[c * 64 + d] = Wv[(h * 64 + d) * 64 + c];
    }
    if (tid < 64) {
        sKb[tid] = kb[h * 64 + tid];
        sVb[tid] = vb[h * 64 + tid];
        sLw[tid] = lnw[h * 64 + tid];
        sLb[tid] = lnb[h * 64 + tid];
    }

    float akv[16];
    #pragma unroll
    for (int i = 0; i < 16; i++) akv[i] = 0.0f;

    const int n_base = b * N_ + chunk * 1024;

    for (int t0 = 0; t0 < 1024; t0 += 64) {
        __syncthreads();   // prev tile consumers of sVt/sK/sU done (also weight fill at t0=0 partly)
        // ---- load v tile [64 tok][64 cin], store transposed sVt[c][tok]
        for (int i = tid; i < 1024; i += 256) {
            int tok = i >> 4, c4 = (i & 15) * 4;
            float4 vv = *(const float4*)&v[(n_base + t0 + tok) * 64 + c4];
            sVt[(c4 + 0) * 68 + tok] = vv.x;
            sVt[(c4 + 1) * 68 + tok] = vv.y;
            sVt[(c4 + 2) * 68 + tok] = vv.z;
            sVt[(c4 + 3) * 68 + tok] = vv.w;
        }
        __syncthreads();

        // ---- proj: K,U for tokens t4..t4+3, dims d4..d4+3
        float ak[16], au[16];
        #pragma unroll
        for (int i = 0; i < 16; i++) { ak[i] = 0.0f; au[i] = 0.0f; }
        #pragma unroll 8
        for (int c = 0; c < 64; c++) {
            float4 a  = *(const float4*)&sVt[c * 68 + t4];
            float4 wk = *(const float4*)&sWk[c * 64 + d4];
            float4 wv = *(const float4*)&sWv[c * 64 + d4];
            op4x4(a, wk, ak);
            op4x4(a, wv, au);
        }
        float4 bk = *(const float4*)&sKb[d4];
        float4 bv = *(const float4*)&sVb[d4];
        #pragma unroll
        for (int i = 0; i < 4; i++) {
            float4 kk = make_float4(ak[i*4+0] + bk.x, ak[i*4+1] + bk.y,
                                    ak[i*4+2] + bk.z, ak[i*4+3] + bk.w);
            float4 uu = make_float4(au[i*4+0] + bv.x, au[i*4+1] + bv.y,
                                    au[i*4+2] + bv.z, au[i*4+3] + bv.w);
            *(float4*)&sK[(t4 + i) * 68 + d4] = kk;
            *(float4*)&sU[(t4 + i) * 68 + d4] = uu;
        }
        __syncthreads();

        // ---- LayerNorm rows of sK (warp w handles rows w*8..w*8+7)
        {
            int w = tid >> 5, lane = tid & 31;
            #pragma unroll
            for (int rr = 0; rr < 8; rr++) {
                int row = w * 8 + rr;
                float x0 = sK[row * 68 + lane], x1 = sK[row * 68 + 32 + lane];
                float s  = x0 + x1;
                float s2 = x0 * x0 + x1 * x1;
                #pragma unroll
                for (int o = 16; o > 0; o >>= 1) {
                    s  += __shfl_xor_sync(0xffffffffu, s,  o);
                    s2 += __shfl_xor_sync(0xffffffffu, s2, o);
                }
                float mu  = s * (1.0f / 64.0f);
                float var = fmaxf(s2 * (1.0f / 64.0f) - mu * mu, 0.0f);
                float inv = rsqrtf(var + 1e-5f);
                sK[row * 68 + lane]      = (x0 - mu) * inv * sLw[lane]      + sLb[lane];
                sK[row * 68 + 32 + lane] = (x1 - mu) * inv * sLw[32 + lane] + sLb[32 + lane];
            }
        }
        __syncthreads();

        // ---- outer: akv[d=t4+i][e=d4+j] += sum_t K[t][t4+i]*U[t][d4+j]
        #pragma unroll 16
        for (int t = 0; t < 64; t++) {
            float4 kk = *(const float4*)&sK[t * 68 + t4];
            float4 uu = *(const float4*)&sU[t * 68 + d4];
            op4x4(kk, uu, akv);
        }
    }

    float* kvp = &g_KV[(b * H_ + h) * 4096];
    #pragma unroll
    for (int i = 0; i < 4; i++)
        #pragma unroll
        for (int j = 0; j < 4; j++)
            atomicAdd(&kvp[(t4 + i) * 64 + d4 + j], akv[i * 4 + j]);
}

// ---------------------------------------------------------------------------
// Kernel 2: fold G[b,h,d,c] = sum_e KV[b,h,d,e] * o_w[c, h*64+e]  (tiny)
// ---------------------------------------------------------------------------
__global__ __launch_bounds__(256) void fold_kernel(const float* __restrict__ ow)
{
    const int h = blockIdx.x, b = blockIdx.y, tid = threadIdx.x;
    __shared__ __align__(16) float sKVt[64][64];  // [e][d]
    __shared__ __align__(16) float sOw[64][64];   // [e][c]

    const float* kvp = &g_KV[(b * H_ + h) * 4096];
    for (int i = tid; i < 4096; i += 256) {
        int d = i >> 6, e = i & 63;
        sKVt[e][d] = kvp[d * 64 + e];
    }
    for (int i = tid; i < 4096; i += 256) {
        int c = i >> 6, e = i & 63;
        sOw[e][c] = ow[c * HD_ + h * 64 + e];
    }
    __syncthreads();

    const int d0 = (tid >> 4) * 4, c0 = (tid & 15) * 4;
    float acc[16];
    #pragma unroll
    for (int i = 0; i < 16; i++) acc[i] = 0.0f;
    #pragma unroll 16
    for (int e = 0; e < 64; e++) {
        float4 kk = *(const float4*)&sKVt[e][d0];
        float4 cc = *(const float4*)&sOw[e][c0];
        op4x4(kk, cc, acc);
    }

    float* gp = &g_G[(b * H_ + h) * 4096];
    #pragma unroll
    for (int i = 0; i < 4; i++)
        #pragma unroll
        for (int j = 0; j < 4; j++)
            gp[(d0 + i) * 64 + c0 + j] = acc[i * 4 + j];
}

// ---------------------------------------------------------------------------
// Kernel 3: grid (64 chunks, B), 256 threads. Block owns 128 tokens (2 tiles).
// Heads outer, tiles inner; out accumulator in registers across heads.
// Dynamic smem layout (floats):
//   sW[64*64] @0, sG[64*64] @4096, sVt[64*132] @8192 ([cin][token], 128 tok),
//   sQ[64*68] @16640 ([token][d], current tile),
//   sQb @20992, sLw @21056, sLb @21120, sOb @21184  (total 21248 f = 84992 B)
// ---------------------------------------------------------------------------
#define QOUT_SMEM_BYTES (21248 * 4)

__global__ __launch_bounds__(256) void qout_kernel(
    const float* __restrict__ v,
    const float* __restrict__ Wq, const float* __restrict__ qb,
    const float* __restrict__ lnw, const float* __restrict__ lnb,
    const float* __restrict__ ob,
    float* __restrict__ out)
{
    extern __shared__ float sm[];
    float* sW  = sm;
    float* sG  = sm + 4096;
    float* sVt = sm + 8192;
    float* sQ  = sm + 16640;
    float* sQb = sm + 20992;
    float* sLw = sm + 21056;
    float* sLb = sm + 21120;
    float* sOb = sm + 21184;

    const int chunk = blockIdx.x, b = blockIdx.y, tid = threadIdx.x;
    const int ty = tid >> 4, tx = tid & 15;
    const int t4 = ty * 4, c4 = tx * 4;

    const int n_base = b * N_ + chunk * 128;

    // load v for 128 tokens, transposed sVt[c][tok]
    for (int i = tid; i < 2048; i += 256) {
        int tok = i >> 4, cc4 = (i & 15) * 4;
        float4 vv = *(const float4*)&v[(n_base + tok) * 64 + cc4];
        sVt[(cc4 + 0) * 132 + tok] = vv.x;
        sVt[(cc4 + 1) * 132 + tok] = vv.y;
        sVt[(cc4 + 2) * 132 + tok] = vv.z;
        sVt[(cc4 + 3) * 132 + tok] = vv.w;
    }
    if (tid < 64) sOb[tid] = ob[tid];

    float oacc[2][16];
    #pragma unroll
    for (int t = 0; t < 2; t++)
        #pragma unroll
        for (int i = 0; i < 16; i++) oacc[t][i] = 0.0f;

    for (int h = 0; h < H_; h++) {
        __syncthreads();   // prev head's sG/sQ readers done; sVt fill (h=0)
        for (int i = tid; i < 4096; i += 256) {
            int d = i >> 6, c = i & 63;
            sW[c * 64 + d] = Wq[(h * 64 + d) * 64 + c];
            sG[i] = g_G[(b * H_ + h) * 4096 + i];
        }
        if (tid < 64) {
            sQb[tid] = qb[h * 64 + tid];
            sLw[tid] = lnw[h * 64 + tid];
            sLb[tid] = lnb[h * 64 + tid];
        }
        __syncthreads();

        #pragma unroll
        for (int tile = 0; tile < 2; tile++) {
            // ---- proj q (tokens tile*64+t4.., dims c4..) into regs
            float aq[16];
            #pragma unroll
            for (int i = 0; i < 16; i++) aq[i] = 0.0f;
            #pragma unroll 8
            for (int c = 0; c < 64; c++) {
                float4 a = *(const float4*)&sVt[c * 132 + tile * 64 + t4];
                float4 w = *(const float4*)&sW[c * 64 + c4];
                op4x4(a, w, aq);
            }
            if (tile == 1) __syncthreads();  // tile0 sQ readers done before overwrite
            float4 bq = *(const float4*)&sQb[c4];
            #pragma unroll
            for (int i = 0; i < 4; i++) {
                float4 qq = make_float4(aq[i*4+0] + bq.x, aq[i*4+1] + bq.y,
                                        aq[i*4+2] + bq.z, aq[i*4+3] + bq.w);
                *(float4*)&sQ[(t4 + i) * 68 + c4] = qq;
            }
            __syncthreads();

            // ---- LN rows of sQ
            {
                int w = tid >> 5, lane = tid & 31;
                #pragma unroll
                for (int rr = 0; rr < 8; rr++) {
                    int row = w * 8 + rr;
                    float x0 = sQ[row * 68 + lane], x1 = sQ[row * 68 + 32 + lane];
                    float s  = x0 + x1;
                    float s2 = x0 * x0 + x1 * x1;
                    #pragma unroll
                    for (int o = 16; o > 0; o >>= 1) {
                        s  += __shfl_xor_sync(0xffffffffu, s,  o);
                        s2 += __shfl_xor_sync(0xffffffffu, s2, o);
                    }
                    float mu  = s * (1.0f / 64.0f);
                    float var = fmaxf(s2 * (1.0f / 64.0f) - mu * mu, 0.0f);
                    float inv = rsqrtf(var + 1e-5f);
                    sQ[row * 68 + lane]      = (x0 - mu) * inv * sLw[lane]      + sLb[lane];
                    sQ[row * 68 + 32 + lane] = (x1 - mu) * inv * sLw[32 + lane] + sLb[32 + lane];
                }
            }
            __syncthreads();

            // ---- oacc[tile][(t4+i, c4+j)] += sum_d q[t][d]*G[d][c]
            float* oa = oacc[tile];
            #pragma unroll 8
            for (int d = 0; d < 64; d++) {
                float4 g = *(const float4*)&sG[d * 64 + c4];
                float q0 = sQ[(t4 + 0) * 68 + d];
                float q1 = sQ[(t4 + 1) * 68 + d];
                float q2 = sQ[(t4 + 2) * 68 + d];
                float q3 = sQ[(t4 + 3) * 68 + d];
                op4x4(make_float4(q0, q1, q2, q3), g, oa);
            }
        }
    }

    const float inv_n = 1.0f / (float)N_;
    float4 bo = *(const float4*)&sOb[c4];
    #pragma unroll
    for (int tile = 0; tile < 2; tile++) {
        #pragma unroll
        for (int i = 0; i < 4; i++) {
            float* oa = &oacc[tile][i * 4];
            float4 o;
            o.x = (oa[0] + bo.x) * inv_n;
            o.y = (oa[1] + bo.y) * inv_n;
            o.z = (oa[2] + bo.z) * inv_n;
            o.w = (oa[3] + bo.w) * inv_n;
            *(float4*)&out[(n_base + tile * 64 + t4 + i) * 64 + c4] = o;
        }
    }
}

// ---------------------------------------------------------------------------
extern "C" void kernel_launch(void* const* d_in, const int* in_sizes, int n_in,
                              void* d_out, int out_size)
{
    const float* v     = (const float*)d_in[0];
    const float* Wq_w  = (const float*)d_in[1];
    const float* Wq_b  = (const float*)d_in[2];
    const float* Wk_w  = (const float*)d_in[3];
    const float* Wk_b  = (const float*)d_in[4];
    const float* Wv_w  = (const float*)d_in[5];
    const float* Wv_b  = (const float*)d_in[6];
    const float* lnq_w = (const float*)d_in[7];
    const float* lnq_b = (const float*)d_in[8];
    const float* lnk_w = (const float*)d_in[9];
    const float* lnk_b = (const float*)d_in[10];
    const float* o_w   = (const float*)d_in[11];
    const float* o_b   = (const float*)d_in[12];
    float* out = (float*)d_out;

    static bool attr_done = false;
    if (!attr_done) {
        cudaFuncSetAttribute(kv_kernel,   cudaFuncAttributeMaxDynamicSharedMemorySize, KV_SMEM_BYTES);
        cudaFuncSetAttribute(qout_kernel, cudaFuncAttributeMaxDynamicSharedMemorySize, QOUT_SMEM_BYTES);
        attr_done = true;
    }

    zero_kv_kernel<<<512, 256>>>();
    kv_kernel<<<dim3(8, H_, B_), 256, KV_SMEM_BYTES>>>(v, Wk_w, Wk_b, Wv_w, Wv_b, lnk_w, lnk_b);
    fold_kernel<<<dim3(H_, B_), 256>>>(o_w);
    qout_kernel<<<dim3(64, B_), 256, QOUT_SMEM_BYTES>>>(v, Wq_w, Wq_b, lnq_w, lnq_b, o_b, out);
}

// round 5
// speedup vs baseline: 3.1215x; 1.1913x over previous
#include <cuda_runtime.h>

// FourierAttention1d — linear attention, reassociated + output-projection folded.
//
//   KV[b,h,d,e] = sum_n LN(v Wk^T + kb)[n,h,d] * (v Wv^T + vb)[n,h,e]
//   G[b,h,d,c]  = sum_e KV[b,h,d,e] * o_w[c, h*64+e]
//   out[b,n,c]  = ( sum_{h,d} LN(v Wq^T + qb)[n,h,d] * G[b,h,d,c] + o_b[c] ) / N
//
// R4 (resubmit after infra timeout): packed f32x2 FFMA (FFMA2) with packing
// along the reduction dimension, register-resident LayerNorm, strided dim
// ownership for bank spread.

#define B_   4
#define N_   8192
#define H_   8
#define HD_  512

typedef unsigned long long u64;

__device__ float g_KV[B_ * H_ * 64 * 64];   // [b][h][d][e]
__device__ float g_G [B_ * H_ * 64 * 64];   // [b][h][d][c]

__global__ void zero_kv_kernel() {
    int i = blockIdx.x * blockDim.x + threadIdx.x;
    if (i < B_ * H_ * 64 * 64) g_KV[i] = 0.0f;
}

// d = a * b + d, packed 2xf32
__device__ __forceinline__ void ffma2(u64& d, u64 a, u64 b) {
    asm("fma.rn.f32x2 %0, %1, %2, %3;" : "=l"(d) : "l"(a), "l"(b), "l"(d));
}
// horizontal add of a packed pair
__device__ __forceinline__ float hadd2(u64 p) {
    float lo, hi;
    asm("mov.b64 {%0, %1}, %2;" : "=f"(lo), "=f"(hi) : "l"(p));
    return lo + hi;
}

// ---------------------------------------------------------------------------
// Kernel 1: grid (8 chunks, H, B), 256 threads, block = (b,h) x 1024 tokens.
// Dynamic smem (floats):
//   sWk[64*68] @0       [d][c]   (straight copy of Wk rows for head h)
//   sWv[64*68] @4352    [d][c]
//   sV [64*68] @8704    [t][c]
//   sKt[64*68] @13056   [d][t]   (LN'ed K, transposed)
//   sUt[64*68] @17408   [e][t]
//   sKb @21760, sVb @21824, sLw @21888, sLb @21952  -> 22016 f = 88064 B
// ---------------------------------------------------------------------------
#define KV_SMEM_BYTES (22016 * 4)

__global__ __launch_bounds__(256, 2) void kv_kernel(
    const float* __restrict__ v,
    const float* __restrict__ Wk, const float* __restrict__ kb,
    const float* __restrict__ Wv, const float* __restrict__ vb,
    const float* __restrict__ lnw, const float* __restrict__ lnb)
{
    extern __shared__ float sm[];
    float* sWk = sm;
    float* sWv = sm + 4352;
    float* sV  = sm + 8704;
    float* sKt = sm + 13056;
    float* sUt = sm + 17408;
    float* sKb = sm + 21760;
    float* sVb = sm + 21824;
    float* sLw = sm + 21888;
    float* sLb = sm + 21952;

    const int chunk = blockIdx.x, h = blockIdx.y, b = blockIdx.z;
    const int tid = threadIdx.x;
    const int ty = tid >> 4, tx = tid & 15;
    const int t4 = ty * 4;                    // token group (proj) / KV d-row group (outer)
    // dims owned (proj output dims / outer e-cols): tx + 16*j, j=0..3

    // stage weights: straight copy (row-major [d][c], stride 68)
    for (int i = tid; i < 1024; i += 256) {
        int d = i >> 4, c4 = (i & 15) * 4;
        *(float4*)&sWk[d * 68 + c4] = *(const float4*)&Wk[(h * 64 + d) * 64 + c4];
        *(float4*)&sWv[d * 68 + c4] = *(const float4*)&Wv[(h * 64 + d) * 64 + c4];
    }
    if (tid < 64) {
        sKb[tid] = kb[h * 64 + tid];
        sVb[tid] = vb[h * 64 + tid];
        sLw[tid] = lnw[h * 64 + tid];
        sLb[tid] = lnb[h * 64 + tid];
    }

    float akv[4][4];
    #pragma unroll
    for (int i = 0; i < 4; i++)
        #pragma unroll
        for (int j = 0; j < 4; j++) akv[i][j] = 0.0f;

    const int n_base = b * N_ + chunk * 1024;

    for (int t0 = 0; t0 < 1024; t0 += 64) {
        __syncthreads();   // prior tile fully consumed (also covers weight fill at t0=0)
        // ---- load v tile [64 tok][64 cin], row-major
        for (int i = tid; i < 1024; i += 256) {
            int t = i >> 4, c4 = (i & 15) * 4;
            *(float4*)&sV[t * 68 + c4] = *(const float4*)&v[(n_base + t0 + t) * 64 + c4];
        }
        __syncthreads();

        float k_s[4][4], u_s[4][4];

        // ---- K projection (packed along c)
        {
            u64 akp[4][4];
            #pragma unroll
            for (int i = 0; i < 4; i++)
                #pragma unroll
                for (int j = 0; j < 4; j++) akp[i][j] = 0ull;
            #pragma unroll 8
            for (int c = 0; c < 64; c += 4) {
                ulonglong2 vq[4], wq[4];
                #pragma unroll
                for (int i = 0; i < 4; i++)
                    vq[i] = *(const ulonglong2*)&sV[(t4 + i) * 68 + c];
                #pragma unroll
                for (int j = 0; j < 4; j++)
                    wq[j] = *(const ulonglong2*)&sWk[(tx + 16 * j) * 68 + c];
                #pragma unroll
                for (int i = 0; i < 4; i++)
                    #pragma unroll
                    for (int j = 0; j < 4; j++) {
                        ffma2(akp[i][j], vq[i].x, wq[j].x);
                        ffma2(akp[i][j], vq[i].y, wq[j].y);
                    }
            }
            #pragma unroll
            for (int i = 0; i < 4; i++)
                #pragma unroll
                for (int j = 0; j < 4; j++)
                    k_s[i][j] = hadd2(akp[i][j]) + sKb[tx + 16 * j];
        }
        // ---- U (=V head) projection (packed along c)
        {
            u64 aup[4][4];
            #pragma unroll
            for (int i = 0; i < 4; i++)
                #pragma unroll
                for (int j = 0; j < 4; j++) aup[i][j] = 0ull;
            #pragma unroll 8
            for (int c = 0; c < 64; c += 4) {
                ulonglong2 vq[4], wq[4];
                #pragma unroll
                for (int i = 0; i < 4; i++)
                    vq[i] = *(const ulonglong2*)&sV[(t4 + i) * 68 + c];
                #pragma unroll
                for (int j = 0; j < 4; j++)
                    wq[j] = *(const ulonglong2*)&sWv[(tx + 16 * j) * 68 + c];
                #pragma unroll
                for (int i = 0; i < 4; i++)
                    #pragma unroll
                    for (int j = 0; j < 4; j++) {
                        ffma2(aup[i][j], vq[i].x, wq[j].x);
                        ffma2(aup[i][j], vq[i].y, wq[j].y);
                    }
            }
            #pragma unroll
            for (int i = 0; i < 4; i++)
                #pragma unroll
                for (int j = 0; j < 4; j++)
                    u_s[i][j] = hadd2(aup[i][j]) + sVb[tx + 16 * j];
        }

        // ---- LayerNorm K in registers (reduce over 64 dims: 4 local + 16 lanes)
        #pragma unroll
        for (int i = 0; i < 4; i++) {
            float s = 0.f, s2 = 0.f;
            #pragma unroll
            for (int j = 0; j < 4; j++) { s += k_s[i][j]; s2 += k_s[i][j] * k_s[i][j]; }
            #pragma unroll
            for (int o = 1; o < 16; o <<= 1) {
                s  += __shfl_xor_sync(0xffffffffu, s,  o);
                s2 += __shfl_xor_sync(0xffffffffu, s2, o);
            }
            float mu  = s * (1.0f / 64.0f);
            float var = fmaxf(s2 * (1.0f / 64.0f) - mu * mu, 0.0f);
            float inv = rsqrtf(var + 1e-5f);
            #pragma unroll
            for (int j = 0; j < 4; j++)
                k_s[i][j] = (k_s[i][j] - mu) * inv * sLw[tx + 16 * j] + sLb[tx + 16 * j];
        }

        // ---- store transposed [d][t] for token-packed outer product
        #pragma unroll
        for (int i = 0; i < 4; i++)
            #pragma unroll
            for (int j = 0; j < 4; j++) {
                sKt[(tx + 16 * j) * 68 + t4 + i] = k_s[i][j];
                sUt[(tx + 16 * j) * 68 + t4 + i] = u_s[i][j];
            }
        __syncthreads();

        // ---- outer product: akv[4ty+i][tx+16j] += sum_t k*u (packed along t)
        {
            u64 akvp[4][4];
            #pragma unroll
            for (int i = 0; i < 4; i++)
                #pragma unroll
                for (int j = 0; j < 4; j++) akvp[i][j] = 0ull;
            #pragma unroll 8
            for (int t = 0; t < 64; t += 4) {
                ulonglong2 kq[4], uq[4];
                #pragma unroll
                for (int i = 0; i < 4; i++)
                    kq[i] = *(const ulonglong2*)&sKt[(t4 + i) * 68 + t];
                #pragma unroll
                for (int j = 0; j < 4; j++)
                    uq[j] = *(const ulonglong2*)&sUt[(tx + 16 * j) * 68 + t];
                #pragma unroll
                for (int i = 0; i < 4; i++)
                    #pragma unroll
                    for (int j = 0; j < 4; j++) {
                        ffma2(akvp[i][j], kq[i].x, uq[j].x);
                        ffma2(akvp[i][j], kq[i].y, uq[j].y);
                    }
            }
            #pragma unroll
            for (int i = 0; i < 4; i++)
                #pragma unroll
                for (int j = 0; j < 4; j++)
                    akv[i][j] += hadd2(akvp[i][j]);
        }
    }

    float* kvp = &g_KV[(b * H_ + h) * 4096];
    #pragma unroll
    for (int i = 0; i < 4; i++)
        #pragma unroll
        for (int j = 0; j < 4; j++)
            atomicAdd(&kvp[(t4 + i) * 64 + tx + 16 * j], akv[i][j]);
}

// ---------------------------------------------------------------------------
// Kernel 2: fold G[b,h,d,c] = sum_e KV[b,h,d,e] * o_w[c, h*64+e]  (tiny)
// ---------------------------------------------------------------------------
__global__ __launch_bounds__(256) void fold_kernel(const float* __restrict__ ow)
{
    const int h = blockIdx.x, b = blockIdx.y, tid = threadIdx.x;
    __shared__ __align__(16) float sKVt[64][64];  // [e][d]
    __shared__ __align__(16) float sOw[64][64];   // [e][c]

    const float* kvp = &g_KV[(b * H_ + h) * 4096];
    for (int i = tid; i < 4096; i += 256) {
        int d = i >> 6, e = i & 63;
        sKVt[e][d] = kvp[d * 64 + e];
    }
    for (int i = tid; i < 4096; i += 256) {
        int c = i >> 6, e = i & 63;
        sOw[e][c] = ow[c * HD_ + h * 64 + e];
    }
    __syncthreads();

    const int d0 = (tid >> 4) * 4, c0 = (tid & 15) * 4;
    float acc[16];
    #pragma unroll
    for (int i = 0; i < 16; i++) acc[i] = 0.0f;
    #pragma unroll 16
    for (int e = 0; e < 64; e++) {
        float4 kk = *(const float4*)&sKVt[e][d0];
        float4 cc = *(const float4*)&sOw[e][c0];
        acc[ 0] = fmaf(kk.x, cc.x, acc[ 0]); acc[ 1] = fmaf(kk.x, cc.y, acc[ 1]);
        acc[ 2] = fmaf(kk.x, cc.z, acc[ 2]); acc[ 3] = fmaf(kk.x, cc.w, acc[ 3]);
        acc[ 4] = fmaf(kk.y, cc.x, acc[ 4]); acc[ 5] = fmaf(kk.y, cc.y, acc[ 5]);
        acc[ 6] = fmaf(kk.y, cc.z, acc[ 6]); acc[ 7] = fmaf(kk.y, cc.w, acc[ 7]);
        acc[ 8] = fmaf(kk.z, cc.x, acc[ 8]); acc[ 9] = fmaf(kk.z, cc.y, acc[ 9]);
        acc[10] = fmaf(kk.z, cc.z, acc[10]); acc[11] = fmaf(kk.z, cc.w, acc[11]);
        acc[12] = fmaf(kk.w, cc.x, acc[12]); acc[13] = fmaf(kk.w, cc.y, acc[13]);
        acc[14] = fmaf(kk.w, cc.z, acc[14]); acc[15] = fmaf(kk.w, cc.w, acc[15]);
    }

    float* gp = &g_G[(b * H_ + h) * 4096];
    #pragma unroll
    for (int i = 0; i < 4; i++)
        #pragma unroll
        for (int j = 0; j < 4; j++)
            gp[(d0 + i) * 64 + c0 + j] = acc[i * 4 + j];
}

// ---------------------------------------------------------------------------
// Kernel 3: grid (64 chunks, B), 256 threads, block = 128 tokens, heads outer.
// Dynamic smem (floats):
//   sWq[64*68] @0       [d][c]  (straight copy)
//   sGt[64*68] @4352    [c][d]  (transposed: pairs along d)
//   sV [128*68] @8704   [t][c]
//   sQ [64*68] @17408   [t][d]  (LN'ed Q, current 64-token tile)
//   sQb @21760, sLw @21824, sLb @21888, sOb @21952 -> 22016 f = 88064 B
// ---------------------------------------------------------------------------
#define QOUT_SMEM_BYTES (22016 * 4)

__global__ __launch_bounds__(256, 2) void qout_kernel(
    const float* __restrict__ v,
    const float* __restrict__ Wq, const float* __restrict__ qb,
    const float* __restrict__ lnw, const float* __restrict__ lnb,
    const float* __restrict__ ob,
    float* __restrict__ out)
{
    extern __shared__ float sm[];
    float* sWq = sm;
    float* sGt = sm + 4352;
    float* sV  = sm + 8704;
    float* sQ  = sm + 17408;
    float* sQb = sm + 21760;
    float* sLw = sm + 21824;
    float* sLb = sm + 21888;
    float* sOb = sm + 21952;

    const int chunk = blockIdx.x, b = blockIdx.y, tid = threadIdx.x;
    const int ty = tid >> 4, tx = tid & 15;
    const int t4 = ty * 4;

    const int n_base = b * N_ + chunk * 128;

    // load v for 128 tokens, row-major [t][c]
    for (int i = tid; i < 2048; i += 256) {
        int t = i >> 4, c4 = (i & 15) * 4;
        *(float4*)&sV[t * 68 + c4] = *(const float4*)&v[(n_base + t) * 64 + c4];
    }
    if (tid < 64) sOb[tid] = ob[tid];

    float oacc[2][4][4];
    #pragma unroll
    for (int t = 0; t < 2; t++)
        #pragma unroll
        for (int i = 0; i < 4; i++)
            #pragma unroll
            for (int j = 0; j < 4; j++) oacc[t][i][j] = 0.0f;

    for (int h = 0; h < H_; h++) {
        __syncthreads();   // prev head done with sWq/sGt/sQ; sV fill done (h=0)
        for (int i = tid; i < 1024; i += 256) {
            int d = i >> 4, c4 = (i & 15) * 4;
            *(float4*)&sWq[d * 68 + c4] = *(const float4*)&Wq[(h * 64 + d) * 64 + c4];
            float4 g = *(const float4*)&g_G[(b * H_ + h) * 4096 + d * 64 + c4];
            sGt[(c4 + 0) * 68 + d] = g.x;
            sGt[(c4 + 1) * 68 + d] = g.y;
            sGt[(c4 + 2) * 68 + d] = g.z;
            sGt[(c4 + 3) * 68 + d] = g.w;
        }
        if (tid < 64) {
            sQb[tid] = qb[h * 64 + tid];
            sLw[tid] = lnw[h * 64 + tid];
            sLb[tid] = lnb[h * 64 + tid];
        }
        __syncthreads();

        #pragma unroll
        for (int tile = 0; tile < 2; tile++) {
            // ---- Q projection (packed along c), tokens tile*64 + t4..t4+3
            float q_s[4][4];
            {
                u64 aqp[4][4];
                #pragma unroll
                for (int i = 0; i < 4; i++)
                    #pragma unroll
                    for (int j = 0; j < 4; j++) aqp[i][j] = 0ull;
                #pragma unroll 8
                for (int c = 0; c < 64; c += 4) {
                    ulonglong2 vq[4], wq[4];
                    #pragma unroll
                    for (int i = 0; i < 4; i++)
                        vq[i] = *(const ulonglong2*)&sV[(tile * 64 + t4 + i) * 68 + c];
                    #pragma unroll
                    for (int j = 0; j < 4; j++)
                        wq[j] = *(const ulonglong2*)&sWq[(tx + 16 * j) * 68 + c];
                    #pragma unroll
                    for (int i = 0; i < 4; i++)
                        #pragma unroll
                        for (int j = 0; j < 4; j++) {
                            ffma2(aqp[i][j], vq[i].x, wq[j].x);
                            ffma2(aqp[i][j], vq[i].y, wq[j].y);
                        }
                }
                #pragma unroll
                for (int i = 0; i < 4; i++)
                    #pragma unroll
                    for (int j = 0; j < 4; j++)
                        q_s[i][j] = hadd2(aqp[i][j]) + sQb[tx + 16 * j];
            }

            // ---- LN Q in registers
            #pragma unroll
            for (int i = 0; i < 4; i++) {
                float s = 0.f, s2 = 0.f;
                #pragma unroll
                for (int j = 0; j < 4; j++) { s += q_s[i][j]; s2 += q_s[i][j] * q_s[i][j]; }
                #pragma unroll
                for (int o = 1; o < 16; o <<= 1) {
                    s  += __shfl_xor_sync(0xffffffffu, s,  o);
                    s2 += __shfl_xor_sync(0xffffffffu, s2, o);
                }
                float mu  = s * (1.0f / 64.0f);
                float var = fmaxf(s2 * (1.0f / 64.0f) - mu * mu, 0.0f);
                float inv = rsqrtf(var + 1e-5f);
                #pragma unroll
                for (int j = 0; j < 4; j++)
                    q_s[i][j] = (q_s[i][j] - mu) * inv * sLw[tx + 16 * j] + sLb[tx + 16 * j];
            }

            if (tile == 1) __syncthreads();  // tile0 readers of sQ done
            #pragma unroll
            for (int i = 0; i < 4; i++)
                #pragma unroll
                for (int j = 0; j < 4; j++)
                    sQ[(t4 + i) * 68 + tx + 16 * j] = q_s[i][j];
            __syncthreads();

            // ---- accumulate out += Q @ G (packed along d)
            {
                u64 oap[4][4];
                #pragma unroll
                for (int i = 0; i < 4; i++)
                    #pragma unroll
                    for (int j = 0; j < 4; j++) oap[i][j] = 0ull;
                #pragma unroll 8
                for (int d = 0; d < 64; d += 4) {
                    ulonglong2 qq[4], gq[4];
                    #pragma unroll
                    for (int i = 0; i < 4; i++)
                        qq[i] = *(const ulonglong2*)&sQ[(t4 + i) * 68 + d];
                    #pragma unroll
                    for (int j = 0; j < 4; j++)
                        gq[j] = *(const ulonglong2*)&sGt[(tx + 16 * j) * 68 + d];
                    #pragma unroll
                    for (int i = 0; i < 4; i++)
                        #pragma unroll
                        for (int j = 0; j < 4; j++) {
                            ffma2(oap[i][j], qq[i].x, gq[j].x);
                            ffma2(oap[i][j], qq[i].y, gq[j].y);
                        }
                }
                #pragma unroll
                for (int i = 0; i < 4; i++)
                    #pragma unroll
                    for (int j = 0; j < 4; j++)
                        oacc[tile][i][j] += hadd2(oap[i][j]);
            }
        }
    }

    const float inv_n = 1.0f / (float)N_;
    #pragma unroll
    for (int tile = 0; tile < 2; tile++)
        #pragma unroll
        for (int i = 0; i < 4; i++)
            #pragma unroll
            for (int j = 0; j < 4; j++)
                out[(n_base + tile * 64 + t4 + i) * 64 + tx + 16 * j] =
                    (oacc[tile][i][j] + sOb[tx + 16 * j]) * inv_n;
}

// ---------------------------------------------------------------------------
extern "C" void kernel_launch(void* const* d_in, const int* in_sizes, int n_in,
                              void* d_out, int out_size)
{
    const float* v     = (const float*)d_in[0];
    const float* Wq_w  = (const float*)d_in[1];
    const float* Wq_b  = (const float*)d_in[2];
    const float* Wk_w  = (const float*)d_in[3];
    const float* Wk_b  = (const float*)d_in[4];
    const float* Wv_w  = (const float*)d_in[5];
    const float* Wv_b  = (const float*)d_in[6];
    const float* lnq_w = (const float*)d_in[7];
    const float* lnq_b = (const float*)d_in[8];
    const float* lnk_w = (const float*)d_in[9];
    const float* lnk_b = (const float*)d_in[10];
    const float* o_w   = (const float*)d_in[11];
    const float* o_b   = (const float*)d_in[12];
    float* out = (float*)d_out;

    static bool attr_done = false;
    if (!attr_done) {
        cudaFuncSetAttribute(kv_kernel,   cudaFuncAttributeMaxDynamicSharedMemorySize, KV_SMEM_BYTES);
        cudaFuncSetAttribute(qout_kernel, cudaFuncAttributeMaxDynamicSharedMemorySize, QOUT_SMEM_BYTES);
        attr_done = true;
    }

    zero_kv_kernel<<<512, 256>>>();
    kv_kernel<<<dim3(8, H_, B_), 256, KV_SMEM_BYTES>>>(v, Wk_w, Wk_b, Wv_w, Wv_b, lnk_w, lnk_b);
    fold_kernel<<<dim3(H_, B_), 256>>>(o_w);
    qout_kernel<<<dim3(64, B_), 256, QOUT_SMEM_BYTES>>>(v, Wq_w, Wq_b, lnq_w, lnq_b, o_b, out);
}